// round 12
// baseline (speedup 1.0000x reference)
#include <cuda_runtime.h>
#include <math.h>
#include <stdint.h>

// Problem constants
#define Bb   8
#define Nn   64
#define Dd   128
#define Hh   4
#define DHh  32
#define Llay 3
#define FFf  512
#define Mm   (Bb*Nn*Nn)   // 32768 tokens

// ---------------- scratch (device globals; no runtime allocation) ----------------
__device__ float g_tok[Mm*Dd];            // 16 MB
__device__ float g_q  [Mm*Dd];
__device__ float g_k  [Mm*Dd];
__device__ float g_v1 [Mm*Dd];
__device__ float g_v2 [Mm*Dd];
__device__ float g_s  [Bb*Hh*Nn*Nn*Nn];   // [b,h,l,i,j]  33.5 MB
__device__ float g_o  [Mm*Dd];
__device__ float g_hid[Mm*FFf];           // 64 MB

// ---------------- helpers ----------------
__device__ __forceinline__ void mma8(float* c, const uint32_t* a, uint32_t b0, uint32_t b1) {
    asm volatile("mma.sync.aligned.m16n8k8.row.col.f32.tf32.tf32.f32 "
                 "{%0,%1,%2,%3}, {%4,%5,%6,%7}, {%8,%9}, {%0,%1,%2,%3};"
                 : "+f"(c[0]), "+f"(c[1]), "+f"(c[2]), "+f"(c[3])
                 : "r"(a[0]), "r"(a[1]), "r"(a[2]), "r"(a[3]), "r"(b0), "r"(b1));
}
__device__ __forceinline__ void cp16(void* dst_smem, const void* src) {
    uint32_t d = (uint32_t)__cvta_generic_to_shared(dst_smem);
    asm volatile("cp.async.cg.shared.global [%0], [%1], 16;" :: "r"(d), "l"(src) : "memory");
}
__device__ __forceinline__ void cp_commit() {
    asm volatile("cp.async.commit_group;" ::: "memory");
}
template<int N>
__device__ __forceinline__ void cp_wait() {
    asm volatile("cp.async.wait_group %0;" :: "n"(N) : "memory");
}

// ---------------- embedding ----------------
__global__ void embed_kernel(const float* __restrict__ x, const float* __restrict__ ea,
                             const int* __restrict__ mask,
                             const float* __restrict__ nW, const float* __restrict__ nb,
                             const float* __restrict__ eW, const float* __restrict__ eb,
                             const float* __restrict__ noe)
{
    int m = blockIdx.x;           // token index (b,i,j)
    int d = threadIdx.x;          // 0..127
    int b = m >> 12;
    int i = (m >> 6) & 63;
    int j = m & 63;
    __shared__ float in_s[16];
    if (i == j) {
        if (d < 16) in_s[d] = x[(b*64+i)*16 + d];
        __syncthreads();
        float acc = nb[d];
        #pragma unroll
        for (int k = 0; k < 16; k++) acc += in_s[k] * nW[k*128 + d];
        g_tok[(size_t)m*128 + d] = acc;
    } else if (mask[m] != 0) {
        if (d < 8) in_s[d] = ea[(size_t)m*8 + d];
        __syncthreads();
        float acc = eb[d];
        #pragma unroll
        for (int k = 0; k < 8; k++) acc += in_s[k] * eW[k*128 + d];
        g_tok[(size_t)m*128 + d] = acc;
    } else {
        g_tok[(size_t)m*128 + d] = noe[d];
    }
}

// ---------------- TF32 tensor-core GEMM: 128x128 CTA tile, BK=32, cp.async double-buffer ----------------
// 256 threads = 8 warps in 2(m) x 4(n); warp tile 64x32 via 4x4 m16n8k8 fragments.
// Dynamic smem: As[2][128][36] | Bs[2][32][136] | ps[128][4] ps2[128][4] pmv[128] prv[128]
// EPI: 0 = plain store, 1 = bias+relu store, 2 = fused residual+bias+LayerNorm into C (Ndim=128,n0=0)
#define AS_OFF   0
#define BS_OFF   (2*128*36)                 // 9216
#define PS_OFF   (BS_OFF + 2*32*136)        // 17920
#define PS2_OFF  (PS_OFF + 512)
#define PMV_OFF  (PS2_OFF + 512)
#define PRV_OFF  (PMV_OFF + 128)
#define GEMM_SMEM ((PRV_OFF + 128) * 4)     // 76800 bytes

template<int EPI>
__device__ __forceinline__ void mma_core(const float* __restrict__ A,
                                         const float* __restrict__ W,
                                         float* __restrict__ C,
                                         const float* __restrict__ bias,
                                         const float* __restrict__ gamma,
                                         const float* __restrict__ beta,
                                         int Ndim, int Kdim, int m0, int n0)
{
    extern __shared__ float smg[];
    float* As  = smg + AS_OFF;    // [buf][m][36]
    float* Bs  = smg + BS_OFF;    // [buf][k][136]
    float* ps  = smg + PS_OFF;    // [128][4]
    float* ps2 = smg + PS2_OFF;   // [128][4]
    float* pmv = smg + PMV_OFF;
    float* prv = smg + PRV_OFF;

    const int t    = threadIdx.x;
    const int lane = t & 31;
    const int w    = t >> 5;
    const int wm   = w >> 2;            // 0..1
    const int wn   = w & 3;             // 0..3
    const int g    = lane >> 2;         // 0..7
    const int tig  = lane & 3;          // 0..3

    float c_[4][4][4];
    #pragma unroll
    for (int mi = 0; mi < 4; mi++)
        #pragma unroll
        for (int ni = 0; ni < 4; ni++)
            #pragma unroll
            for (int r = 0; r < 4; r++) c_[mi][ni][r] = 0.f;

    auto issue = [&](int kb, int buf) {
        float* Ab = As + buf*128*36;
        float* Bb_ = Bs + buf*32*136;
        #pragma unroll
        for (int q = 0; q < 4; q++) {          // A tile: 128 rows x 32k = 1024 float4
            int idx = q*256 + t;
            int m = idx >> 3, f4 = idx & 7;
            cp16(Ab + m*36 + f4*4, A + (size_t)(m0+m)*Kdim + kb*32 + f4*4);
        }
        #pragma unroll
        for (int q = 0; q < 4; q++) {          // B tile: 32k x 128n = 1024 float4
            int idx = q*256 + t;
            int k = idx >> 5, n4 = idx & 31;
            cp16(Bb_ + k*136 + n4*4, W + (size_t)(kb*32+k)*Ndim + n0 + n4*4);
        }
        cp_commit();
    };

    issue(0, 0);
    const int nk = Kdim >> 5;
    for (int kb = 0; kb < nk; kb++) {
        const int cur = kb & 1;
        cp_wait<0>();
        __syncthreads();
        if (kb + 1 < nk) issue(kb+1, cur ^ 1);
        float* Ab = As + cur*128*36;
        float* Bb_ = Bs + cur*32*136;

        #pragma unroll
        for (int k8 = 0; k8 < 32; k8 += 8) {
            uint32_t af[4][4];
            #pragma unroll
            for (int mi = 0; mi < 4; mi++) {
                int mm = wm*64 + mi*16 + g;
                af[mi][0] = __float_as_uint(Ab[(mm  )*36 + k8+tig]);
                af[mi][1] = __float_as_uint(Ab[(mm+8)*36 + k8+tig]);
                af[mi][2] = __float_as_uint(Ab[(mm  )*36 + k8+tig+4]);
                af[mi][3] = __float_as_uint(Ab[(mm+8)*36 + k8+tig+4]);
            }
            uint32_t bf[4][2];
            #pragma unroll
            for (int ni = 0; ni < 4; ni++) {
                int nn = wn*32 + ni*8 + g;
                bf[ni][0] = __float_as_uint(Bb_[(k8+tig  )*136 + nn]);
                bf[ni][1] = __float_as_uint(Bb_[(k8+tig+4)*136 + nn]);
            }
            #pragma unroll
            for (int mi = 0; mi < 4; mi++)
                #pragma unroll
                for (int ni = 0; ni < 4; ni++)
                    mma8(c_[mi][ni], af[mi], bf[ni][0], bf[ni][1]);
        }
    }

    if (EPI == 2) {
        // fused residual + bias + LayerNorm; Ndim==128, n0==0, C == tok (also residual)
        float bi[4][2], gm[4][2], bt[4][2];
        #pragma unroll
        for (int ni = 0; ni < 4; ni++) {
            int col = wn*32 + ni*8 + 2*tig;
            float2 v;
            v = *(const float2*)(bias  + col); bi[ni][0] = v.x; bi[ni][1] = v.y;
            v = *(const float2*)(gamma + col); gm[ni][0] = v.x; gm[ni][1] = v.y;
            v = *(const float2*)(beta  + col); bt[ni][0] = v.x; bt[ni][1] = v.y;
        }
        #pragma unroll
        for (int mi = 0; mi < 4; mi++) {
            #pragma unroll
            for (int hh = 0; hh < 2; hh++) {
                int lrow = wm*64 + mi*16 + g + hh*8;
                size_t m = (size_t)(m0 + lrow);
                float s = 0.f, s2 = 0.f;
                #pragma unroll
                for (int ni = 0; ni < 4; ni++) {
                    int col = wn*32 + ni*8 + 2*tig;
                    float2 res = *(const float2*)(C + m*128 + col);
                    float v0 = c_[mi][ni][hh*2+0] + res.x + bi[ni][0];
                    float v1 = c_[mi][ni][hh*2+1] + res.y + bi[ni][1];
                    c_[mi][ni][hh*2+0] = v0;
                    c_[mi][ni][hh*2+1] = v1;
                    s += v0 + v1; s2 += v0*v0 + v1*v1;
                }
                // quad reduce over tig (lanes g*4+tig)
                s  += __shfl_xor_sync(0xffffffffu, s,  1);
                s  += __shfl_xor_sync(0xffffffffu, s,  2);
                s2 += __shfl_xor_sync(0xffffffffu, s2, 1);
                s2 += __shfl_xor_sync(0xffffffffu, s2, 2);
                if (tig == 0) { ps[lrow*4 + wn] = s; ps2[lrow*4 + wn] = s2; }
            }
        }
        __syncthreads();
        if (t < 128) {
            float s  = ps [t*4+0] + ps [t*4+1] + ps [t*4+2] + ps [t*4+3];
            float s2 = ps2[t*4+0] + ps2[t*4+1] + ps2[t*4+2] + ps2[t*4+3];
            float mean = s * (1.f/128.f);
            float var  = s2 * (1.f/128.f) - mean*mean;
            pmv[t] = mean;
            prv[t] = rsqrtf(var + 1e-5f);
        }
        __syncthreads();
        #pragma unroll
        for (int mi = 0; mi < 4; mi++) {
            #pragma unroll
            for (int hh = 0; hh < 2; hh++) {
                int lrow = wm*64 + mi*16 + g + hh*8;
                size_t m = (size_t)(m0 + lrow);
                float mean = pmv[lrow], r = prv[lrow];
                #pragma unroll
                for (int ni = 0; ni < 4; ni++) {
                    int col = wn*32 + ni*8 + 2*tig;
                    float2 o;
                    o.x = (c_[mi][ni][hh*2+0] - mean) * r * gm[ni][0] + bt[ni][0];
                    o.y = (c_[mi][ni][hh*2+1] - mean) * r * gm[ni][1] + bt[ni][1];
                    *(float2*)(C + m*128 + col) = o;
                }
            }
        }
    } else {
        #pragma unroll
        for (int mi = 0; mi < 4; mi++) {
            #pragma unroll
            for (int hh = 0; hh < 2; hh++) {
                size_t m = (size_t)(m0 + wm*64 + mi*16 + g + hh*8);
                #pragma unroll
                for (int ni = 0; ni < 4; ni++) {
                    int col = n0 + wn*32 + ni*8 + 2*tig;
                    float v0 = c_[mi][ni][hh*2+0];
                    float v1 = c_[mi][ni][hh*2+1];
                    if (EPI == 1) {
                        v0 = fmaxf(v0 + bias[col],   0.f);
                        v1 = fmaxf(v1 + bias[col+1], 0.f);
                    }
                    float2 o; o.x = v0; o.y = v1;
                    *(float2*)(C + m * Ndim + col) = o;
                }
            }
        }
    }
}

struct Ptr8 { const float* w[4]; float* c[4]; };

__global__ void __launch_bounds__(256, 2) sgemm4_kernel(const float* A, Ptr8 p)
{
    mma_core<0>(A, p.w[blockIdx.z], p.c[blockIdx.z], nullptr, nullptr, nullptr,
                128, 128, blockIdx.y * 128, 0);
}
__global__ void __launch_bounds__(256, 2) sgemm_bias_relu_kernel(const float* A, const float* W,
                                                                 float* C, const float* bias,
                                                                 int Ndim, int Kdim)
{
    mma_core<1>(A, W, C, bias, nullptr, nullptr, Ndim, Kdim,
                blockIdx.y * 128, blockIdx.x * 128);
}
__global__ void __launch_bounds__(256, 2) sgemm_ln_kernel(const float* A, const float* W,
                                                          float* TOK, const float* bias,
                                                          const float* gamma, const float* beta,
                                                          int Kdim)
{
    mma_core<2>(A, W, TOK, bias, gamma, beta, 128, Kdim, blockIdx.y * 128, 0);
}

// ---------------- attention scores: s[b,h,l,i,j] = Q_l @ K_l^T / sqrt(DH) ----------------
__global__ void __launch_bounds__(256) scores_kernel()
{
    int lin = blockIdx.x;          // (b,h,l)
    int l = lin & 63, h = (lin >> 6) & 3, b = lin >> 8;
    __shared__ float Qs[32][68];   // [d][i]
    __shared__ float Ks[32][68];   // [d][j]
    for (int e = threadIdx.x; e < 2048; e += 256) {
        int i = e >> 5, d = e & 31;
        Qs[d][i] = g_q[((size_t)((b*64+i)*64 + l))*128 + h*32 + d];
        Ks[d][i] = g_k[((size_t)((b*64+l)*64 + i))*128 + h*32 + d];
    }
    __syncthreads();
    int ti = threadIdx.x >> 4, tj = threadIdx.x & 15;
    int i0 = ti*4, j0 = tj*4;
    float acc[4][4];
    #pragma unroll
    for (int a = 0; a < 4; a++)
        #pragma unroll
        for (int c = 0; c < 4; c++) acc[a][c] = 0.f;
    #pragma unroll
    for (int d = 0; d < 32; d++) {
        float4 ra = *(const float4*)&Qs[d][i0];
        float4 rb = *(const float4*)&Ks[d][j0];
        float A[4] = {ra.x, ra.y, ra.z, ra.w};
        float Bv[4] = {rb.x, rb.y, rb.z, rb.w};
        #pragma unroll
        for (int ii = 0; ii < 4; ii++)
            #pragma unroll
            for (int jj = 0; jj < 4; jj++)
                acc[ii][jj] += A[ii] * Bv[jj];
    }
    const float isc = 0.17677669529663687f;   // 1/sqrt(32)
    float* sp = g_s + ((size_t)((b*4+h)*64 + l)) * 4096;
    #pragma unroll
    for (int ii = 0; ii < 4; ii++) {
        float4 v = make_float4(acc[ii][0]*isc, acc[ii][1]*isc, acc[ii][2]*isc, acc[ii][3]*isc);
        *(float4*)(sp + (i0+ii)*64 + j0) = v;
    }
}

// ---------------- combine + fused softmax over l (Round-9 best variant) ----------------
// o[b,i,j,h,d] = sum_l softmax_l(s)[b,h,l,i,j] * v1[b,i,l,h,d] * v2[b,l,j,h,d]
// i-tiled by 4. Thread map: t = j*8 + dg. v2 from gmem with depth-2 register ring; l unrolled x2.
// a4 ii-innermost: a4[l*256 + j*4 + ii]. dyn smem: a4[64][64][4] | v1s[4][64][32] | invs[64][4]
#define CMB_SMEM ((16384 + 8192 + 256) * 4)
__global__ void __launch_bounds__(512, 2) combine_kernel()
{
    extern __shared__ float smc[];
    float* a4   = smc;            // [l*256 + j*4 + ii]  raw s -> exp(s - max)
    float* v1s  = smc + 16384;    // [ii*2048 + l*32 + d]
    float* invs = smc + 24576;    // [j*4 + ii] = 1/sum

    int lin = blockIdx.x;        // (b,h,i4)
    int i4 = lin & 15, h = (lin >> 4) & 3, b = lin >> 6;
    int t = threadIdx.x;
    int j = t >> 3, dg = t & 7;  // dg 0..7, 4 d's each

    const float* abase = g_s + ((size_t)(b*4+h))*262144;
    for (int e = t; e < 16384; e += 512) {
        int ii = e >> 12, l = (e >> 6) & 63, jj = e & 63;
        a4[l*256 + jj*4 + ii] = abase[(size_t)l*4096 + (i4*4+ii)*64 + jj];
    }
    for (int e = t; e < 8192; e += 512) {
        int ii = e >> 11, l = (e >> 5) & 63, d = e & 31;
        v1s[ii*2048 + l*32 + d] = g_v1[((size_t)((b*64+i4*4+ii)*64 + l))*128 + h*32 + d];
    }
    __syncthreads();   // a4/v1s visible

    // ---- softmax over l for each (ii, j): 2 threads per column (halves of l) ----
    {
        int col = t >> 1, half = t & 1;     // col 0..255 -> (j = col>>2, ii = col&3)
        float* sp = a4 + col + half*32*256;
        float mx = -1e30f;
        #pragma unroll 4
        for (int l = 0; l < 32; l++) mx = fmaxf(mx, sp[l*256]);
        mx = fmaxf(mx, __shfl_xor_sync(0xffffffffu, mx, 1));
        float sum = 0.f;
        #pragma unroll 4
        for (int l = 0; l < 32; l++) { float e = __expf(sp[l*256] - mx); sp[l*256] = e; sum += e; }
        sum += __shfl_xor_sync(0xffffffffu, sum, 1);
        if (half == 0) invs[col] = 1.f / sum;
    }
    __syncthreads();

    float acc[4][4];
    #pragma unroll
    for (int ii = 0; ii < 4; ii++)
        #pragma unroll
        for (int k = 0; k < 4; k++) acc[ii][k] = 0.f;

    // v2 pointer for this thread's (j, dg): advance by l (stride 64*128 floats)
    const float* v2p = g_v2 + ((size_t)(b*64)*64 + j)*128 + h*32 + dg*4;
    const size_t v2step = (size_t)64*128;

    float4 nv0 = *(const float4*)(v2p);              // prefetch l=0
    float4 nv1 = *(const float4*)(v2p + v2step);     // prefetch l=1
    #pragma unroll 2
    for (int l = 0; l < 64; l += 2) {
        float4 va = nv0, vb = nv1;
        if (l + 2 < 64) nv0 = *(const float4*)(v2p + (size_t)(l+2)*v2step);
        if (l + 3 < 64) nv1 = *(const float4*)(v2p + (size_t)(l+3)*v2step);
        {
            float4 av4 = *(const float4*)&a4[l*256 + j*4];
            float aa[4] = {av4.x, av4.y, av4.z, av4.w};
            #pragma unroll
            for (int ii = 0; ii < 4; ii++) {
                const float4 v1v = *(const float4*)&v1s[ii*2048 + l*32 + dg*4];
                acc[ii][0] += aa[ii] * v1v.x * va.x;
                acc[ii][1] += aa[ii] * v1v.y * va.y;
                acc[ii][2] += aa[ii] * v1v.z * va.z;
                acc[ii][3] += aa[ii] * v1v.w * va.w;
            }
        }
        {
            float4 av4 = *(const float4*)&a4[(l+1)*256 + j*4];
            float aa[4] = {av4.x, av4.y, av4.z, av4.w};
            #pragma unroll
            for (int ii = 0; ii < 4; ii++) {
                const float4 v1v = *(const float4*)&v1s[ii*2048 + (l+1)*32 + dg*4];
                acc[ii][0] += aa[ii] * v1v.x * vb.x;
                acc[ii][1] += aa[ii] * v1v.y * vb.y;
                acc[ii][2] += aa[ii] * v1v.z * vb.z;
                acc[ii][3] += aa[ii] * v1v.w * vb.w;
            }
        }
    }

    float4 iv = *(const float4*)&invs[j*4];
    float inv4[4] = {iv.x, iv.y, iv.z, iv.w};

    #pragma unroll
    for (int ii = 0; ii < 4; ii++) {
        int i = i4*4 + ii;
        float4 v = make_float4(acc[ii][0]*inv4[ii], acc[ii][1]*inv4[ii],
                               acc[ii][2]*inv4[ii], acc[ii][3]*inv4[ii]);
        *(float4*)(g_o + ((size_t)((b*64+i)*64 + j))*128 + h*32 + dg*4) = v;
    }
}

// ---------------- final head: out[b,n] = tok[b,n,n,:] @ Wout + bout ----------------
__global__ void out_kernel(const float* __restrict__ Wout, const float* __restrict__ bout,
                           float* __restrict__ out)
{
    int bn = blockIdx.x, d = threadIdx.x;
    int b = bn >> 6, n = bn & 63;
    float v = g_tok[((size_t)((b*64+n)*64 + n))*128 + d] * Wout[d];
    #pragma unroll
    for (int o = 16; o; o >>= 1) v += __shfl_xor_sync(0xffffffffu, v, o);
    __shared__ float ws[4];
    if ((d & 31) == 0) ws[d >> 5] = v;
    __syncthreads();
    if (d == 0) out[bn] = ws[0] + ws[1] + ws[2] + ws[3] + bout[0];
}

// ---------------- host orchestration ----------------
extern "C" void kernel_launch(void* const* d_in, const int* in_sizes, int n_in,
                              void* d_out, int out_size)
{
    const float* x    = (const float*)d_in[0];
    const float* ea   = (const float*)d_in[1];
    const int*   mask = (const int*)d_in[2];
    const float* nW   = (const float*)d_in[3];
    const float* nb   = (const float*)d_in[4];
    const float* eW   = (const float*)d_in[5];
    const float* eb   = (const float*)d_in[6];
    const float* noe  = (const float*)d_in[7];
    const float* Wq   = (const float*)d_in[8];
    const float* Wk   = (const float*)d_in[9];
    const float* Wv1  = (const float*)d_in[10];
    const float* Wv2  = (const float*)d_in[11];
    const float* Wo   = (const float*)d_in[12];
    const float* bo   = (const float*)d_in[13];
    const float* ln1g = (const float*)d_in[14];
    const float* ln1b = (const float*)d_in[15];
    const float* W1   = (const float*)d_in[16];
    const float* b1   = (const float*)d_in[17];
    const float* W2   = (const float*)d_in[18];
    const float* b2   = (const float*)d_in[19];
    const float* ln2g = (const float*)d_in[20];
    const float* ln2b = (const float*)d_in[21];
    const float* Wout = (const float*)d_in[22];
    const float* bout = (const float*)d_in[23];
    float* out = (float*)d_out;

    float *tok, *q, *k, *v1, *v2, *o, *hid;
    cudaGetSymbolAddress((void**)&tok, g_tok);
    cudaGetSymbolAddress((void**)&q,   g_q);
    cudaGetSymbolAddress((void**)&k,   g_k);
    cudaGetSymbolAddress((void**)&v1,  g_v1);
    cudaGetSymbolAddress((void**)&v2,  g_v2);
    cudaGetSymbolAddress((void**)&o,   g_o);
    cudaGetSymbolAddress((void**)&hid, g_hid);

    cudaFuncSetAttribute(combine_kernel, cudaFuncAttributeMaxDynamicSharedMemorySize, CMB_SMEM);
    cudaFuncSetAttribute(sgemm4_kernel, cudaFuncAttributeMaxDynamicSharedMemorySize, GEMM_SMEM);
    cudaFuncSetAttribute(sgemm_bias_relu_kernel, cudaFuncAttributeMaxDynamicSharedMemorySize, GEMM_SMEM);
    cudaFuncSetAttribute(sgemm_ln_kernel, cudaFuncAttributeMaxDynamicSharedMemorySize, GEMM_SMEM);

    embed_kernel<<<Mm, 128>>>(x, ea, mask, nW, nb, eW, eb, noe);

    for (int l = 0; l < Llay; l++) {
        Ptr8 p;
        p.w[0] = Wq  + (size_t)l*128*128;
        p.w[1] = Wk  + (size_t)l*128*128;
        p.w[2] = Wv1 + (size_t)l*128*128;
        p.w[3] = Wv2 + (size_t)l*128*128;
        p.c[0] = q; p.c[1] = k; p.c[2] = v1; p.c[3] = v2;
        sgemm4_kernel<<<dim3(1, Mm/128, 4), 256, GEMM_SMEM>>>(tok, p);

        scores_kernel <<<Bb*Hh*Nn, 256>>>();
        combine_kernel<<<Bb*Hh*(Nn/4), 512, CMB_SMEM>>>();

        // tok = LN(tok + o@Wo + bo)   (fused epilogue)
        sgemm_ln_kernel<<<dim3(1, Mm/128), 256, GEMM_SMEM>>>(o, Wo + (size_t)l*128*128, tok,
                                                  bo + l*128, ln1g + l*128, ln1b + l*128, 128);

        // ff
        sgemm_bias_relu_kernel<<<dim3(FFf/128, Mm/128), 256, GEMM_SMEM>>>(tok, W1 + (size_t)l*128*512,
                                                               hid, b1 + l*512, 512, 128);
        // tok = LN(tok + hid@W2 + b2) (fused epilogue)
        sgemm_ln_kernel<<<dim3(1, Mm/128), 256, GEMM_SMEM>>>(hid, W2 + (size_t)l*512*128, tok,
                                                  b2 + l*128, ln2g + l*128, ln2b + l*128, 512);
    }

    out_kernel<<<Bb*Nn, 128>>>(Wout, bout, out);
}

// round 14
// speedup vs baseline: 1.1612x; 1.1612x over previous
#include <cuda_runtime.h>
#include <cuda_fp16.h>
#include <math.h>
#include <stdint.h>

// Problem constants
#define Bb   8
#define Nn   64
#define Dd   128
#define Hh   4
#define DHh  32
#define Llay 3
#define FFf  512
#define Mm   (Bb*Nn*Nn)   // 32768 tokens

// ---------------- scratch (device globals; no runtime allocation) ----------------
__device__ float  g_tok [Mm*Dd];           // fp32 tok (residual/LN/out)
__device__ __half g_tok16[Mm*Dd];          // fp16 shadow (GEMM A input)
__device__ float  g_q  [Mm*Dd];
__device__ float  g_k  [Mm*Dd];
__device__ float  g_v1 [Mm*Dd];
__device__ float  g_v2 [Mm*Dd];
__device__ float  g_s  [Bb*Hh*Nn*Nn*Nn];   // [b,h,l,i,j]
__device__ __half g_o16 [Mm*Dd];           // combine output (only GEMM consumes)
__device__ __half g_hid16[Mm*FFf];         // FF hidden (only GEMM consumes)
// packed fp16 weights: [k/2][n][2] per (weight, layer)
//  Wq 0 | Wk 49152 | Wv1 98304 | Wv2 147456 | Wo 196608 | W1 245760 | W2 442368 ; total 638976
__device__ __half g_w16[638976];

// ---------------- helpers ----------------
__device__ __forceinline__ void mma16(float* c, const uint32_t* a, uint32_t b0, uint32_t b1) {
    asm volatile("mma.sync.aligned.m16n8k16.row.col.f32.f16.f16.f32 "
                 "{%0,%1,%2,%3}, {%4,%5,%6,%7}, {%8,%9}, {%0,%1,%2,%3};"
                 : "+f"(c[0]), "+f"(c[1]), "+f"(c[2]), "+f"(c[3])
                 : "r"(a[0]), "r"(a[1]), "r"(a[2]), "r"(a[3]), "r"(b0), "r"(b1));
}
__device__ __forceinline__ void cp16(void* dst_smem, const void* src) {
    uint32_t d = (uint32_t)__cvta_generic_to_shared(dst_smem);
    asm volatile("cp.async.cg.shared.global [%0], [%1], 16;" :: "r"(d), "l"(src) : "memory");
}
__device__ __forceinline__ void cp_commit() {
    asm volatile("cp.async.commit_group;" ::: "memory");
}
template<int N>
__device__ __forceinline__ void cp_wait() {
    asm volatile("cp.async.wait_group %0;" :: "n"(N) : "memory");
}

// ---------------- weight conversion: fp32 -> packed fp16 [k/2][n][2] ----------------
__global__ void wconv_kernel(const float* __restrict__ Wq, const float* __restrict__ Wk,
                             const float* __restrict__ Wv1, const float* __restrict__ Wv2,
                             const float* __restrict__ Wo, const float* __restrict__ W1,
                             const float* __restrict__ W2)
{
    int e = blockIdx.x*256 + threadIdx.x;
    if (e >= 638976) return;
    const float* src; int dst;
    if (e < 245760) {
        int seg = e / 49152, r = e % 49152;
        const float* tab[5] = {Wq, Wk, Wv1, Wv2, Wo};
        src = tab[seg] + r;
        int l = r >> 14, rr = r & 16383, k = rr >> 7, n = rr & 127;
        dst = seg*49152 + l*16384 + (k>>1)*256 + n*2 + (k&1);
    } else if (e < 442368) {
        int r = e - 245760;
        src = W1 + r;
        int l = r >> 16, rr = r & 65535, k = rr >> 9, n = rr & 511;
        dst = 245760 + l*65536 + (k>>1)*1024 + n*2 + (k&1);
    } else {
        int r = e - 442368;
        src = W2 + r;
        int l = r >> 16, rr = r & 65535, k = rr >> 7, n = rr & 127;
        dst = 442368 + l*65536 + (k>>1)*256 + n*2 + (k&1);
    }
    g_w16[dst] = __float2half(*src);
}

// ---------------- embedding ----------------
__global__ void embed_kernel(const float* __restrict__ x, const float* __restrict__ ea,
                             const int* __restrict__ mask,
                             const float* __restrict__ nW, const float* __restrict__ nb,
                             const float* __restrict__ eW, const float* __restrict__ eb,
                             const float* __restrict__ noe)
{
    int m = blockIdx.x;           // token index (b,i,j)
    int d = threadIdx.x;          // 0..127
    int b = m >> 12;
    int i = (m >> 6) & 63;
    int j = m & 63;
    __shared__ float in_s[16];
    float acc;
    if (i == j) {
        if (d < 16) in_s[d] = x[(b*64+i)*16 + d];
        __syncthreads();
        acc = nb[d];
        #pragma unroll
        for (int k = 0; k < 16; k++) acc += in_s[k] * nW[k*128 + d];
    } else if (mask[m] != 0) {
        if (d < 8) in_s[d] = ea[(size_t)m*8 + d];
        __syncthreads();
        acc = eb[d];
        #pragma unroll
        for (int k = 0; k < 8; k++) acc += in_s[k] * eW[k*128 + d];
    } else {
        acc = noe[d];
    }
    g_tok  [(size_t)m*128 + d] = acc;
    g_tok16[(size_t)m*128 + d] = __float2half(acc);
}

// ---------------- FP16 tensor-core GEMM: 128x128 CTA tile, BK=32, cp.async double-buffer ----------------
// 128 threads = 4 warps in 2(m) x 2(n); warp tile 64x64 via 4x8 m16n8k16 fragments.
// A: fp16 row-major [M][K]. W: packed fp16 [k/2][n][2] (u32 col n per k2-row, row = Ndim u32).
// smem: As[2][128][40] half | Bs[2][16][136] u32 | ps[128][2] ps2[128][2] pmv[128] prv[128] (fp32)
// EPI: 0 = fp32 store to C, 1 = bias+relu fp16 store to C16, 2 = residual+bias+LN -> C fp32 + C16 fp16
#define AS_B   0
#define BS_B   20480
#define PS_B   37888
#define PS2_B  (PS_B + 1024)
#define PMV_B  (PS2_B + 1024)
#define PRV_B  (PMV_B + 512)
#define GEMM_SMEM (PRV_B + 512)     // 40448 bytes

template<int EPI>
__device__ __forceinline__ void mma_core(const __half* __restrict__ A16,
                                         const uint32_t* __restrict__ W16,
                                         float* __restrict__ C,
                                         __half* __restrict__ C16,
                                         const float* __restrict__ bias,
                                         const float* __restrict__ gamma,
                                         const float* __restrict__ beta,
                                         int Ndim, int Kdim, int m0, int n0)
{
    extern __shared__ char smraw[];
    __half*   As  = (__half*)(smraw + AS_B);    // [buf][m][40]
    uint32_t* Bs  = (uint32_t*)(smraw + BS_B);  // [buf][k2][136]
    float* ps  = (float*)(smraw + PS_B);
    float* ps2 = (float*)(smraw + PS2_B);
    float* pmv = (float*)(smraw + PMV_B);
    float* prv = (float*)(smraw + PRV_B);

    const int t    = threadIdx.x;
    const int lane = t & 31;
    const int w    = t >> 5;
    const int wm   = w >> 1;            // 0..1
    const int wn   = w & 1;             // 0..1
    const int g    = lane >> 2;         // 0..7
    const int tig  = lane & 3;          // 0..3

    float c_[4][8][4];
    #pragma unroll
    for (int mi = 0; mi < 4; mi++)
        #pragma unroll
        for (int ni = 0; ni < 8; ni++)
            #pragma unroll
            for (int r = 0; r < 4; r++) c_[mi][ni][r] = 0.f;

    auto issue = [&](int kb, int buf) {
        __half* Ab = As + buf*128*40;
        uint32_t* Bb_ = Bs + buf*16*136;
        #pragma unroll
        for (int q = 0; q < 4; q++) {          // A: 128 rows x 32 halfs = 512 chunks of 16B
            int idx = q*128 + t;
            int m = idx >> 2, c = idx & 3;
            cp16(Ab + m*40 + c*8, A16 + (size_t)(m0+m)*Kdim + kb*32 + c*8);
        }
        #pragma unroll
        for (int q = 0; q < 4; q++) {          // B: 16 k2-rows x 128 u32 = 512 chunks
            int idx = q*128 + t;
            int k2 = idx >> 5, c = idx & 31;
            cp16(Bb_ + k2*136 + c*4, W16 + (size_t)(kb*16+k2)*Ndim + n0 + c*4);
        }
        cp_commit();
    };

    issue(0, 0);
    const int nk = Kdim >> 5;
    for (int kb = 0; kb < nk; kb++) {
        const int cur = kb & 1;
        cp_wait<0>();
        __syncthreads();
        if (kb + 1 < nk) issue(kb+1, cur ^ 1);
        __half* Ab = As + cur*128*40;
        uint32_t* Bb_ = Bs + cur*16*136;

        #pragma unroll
        for (int s = 0; s < 2; s++) {          // two m16n8k16 steps per BK=32
            uint32_t af[4][4];
            #pragma unroll
            for (int mi = 0; mi < 4; mi++) {
                int mm = wm*64 + mi*16 + g;
                af[mi][0] = *(const uint32_t*)&Ab[(mm  )*40 + s*16 + 2*tig];
                af[mi][1] = *(const uint32_t*)&Ab[(mm+8)*40 + s*16 + 2*tig];
                af[mi][2] = *(const uint32_t*)&Ab[(mm  )*40 + s*16 + 2*tig + 8];
                af[mi][3] = *(const uint32_t*)&Ab[(mm+8)*40 + s*16 + 2*tig + 8];
            }
            uint32_t bf[8][2];
            #pragma unroll
            for (int ni = 0; ni < 8; ni++) {
                int nn = wn*64 + ni*8 + g;
                bf[ni][0] = Bb_[(s*8 + tig    )*136 + nn];
                bf[ni][1] = Bb_[(s*8 + tig + 4)*136 + nn];
            }
            #pragma unroll
            for (int mi = 0; mi < 4; mi++)
                #pragma unroll
                for (int ni = 0; ni < 8; ni++)
                    mma16(c_[mi][ni], af[mi], bf[ni][0], bf[ni][1]);
        }
    }

    if (EPI == 2) {
        // fused residual + bias + LayerNorm; Ndim==128, n0==0; writes C fp32 and C16 fp16
        float bi[8][2], gm[8][2], bt[8][2];
        #pragma unroll
        for (int ni = 0; ni < 8; ni++) {
            int col = wn*64 + ni*8 + 2*tig;
            float2 v;
            v = *(const float2*)(bias  + col); bi[ni][0] = v.x; bi[ni][1] = v.y;
            v = *(const float2*)(gamma + col); gm[ni][0] = v.x; gm[ni][1] = v.y;
            v = *(const float2*)(beta  + col); bt[ni][0] = v.x; bt[ni][1] = v.y;
        }
        #pragma unroll
        for (int mi = 0; mi < 4; mi++) {
            #pragma unroll
            for (int hh = 0; hh < 2; hh++) {
                int lrow = wm*64 + mi*16 + g + hh*8;
                size_t m = (size_t)(m0 + lrow);
                float s = 0.f, s2 = 0.f;
                #pragma unroll
                for (int ni = 0; ni < 8; ni++) {
                    int col = wn*64 + ni*8 + 2*tig;
                    float2 res = *(const float2*)(C + m*128 + col);
                    float v0 = c_[mi][ni][hh*2+0] + res.x + bi[ni][0];
                    float v1 = c_[mi][ni][hh*2+1] + res.y + bi[ni][1];
                    c_[mi][ni][hh*2+0] = v0;
                    c_[mi][ni][hh*2+1] = v1;
                    s += v0 + v1; s2 += v0*v0 + v1*v1;
                }
                s  += __shfl_xor_sync(0xffffffffu, s,  1);
                s  += __shfl_xor_sync(0xffffffffu, s,  2);
                s2 += __shfl_xor_sync(0xffffffffu, s2, 1);
                s2 += __shfl_xor_sync(0xffffffffu, s2, 2);
                if (tig == 0) { ps[lrow*2 + wn] = s; ps2[lrow*2 + wn] = s2; }
            }
        }
        __syncthreads();
        if (t < 128) {
            float s = ps[t*2+0] + ps[t*2+1];
            float s2 = ps2[t*2+0] + ps2[t*2+1];
            float mean = s * (1.f/128.f);
            float var  = s2 * (1.f/128.f) - mean*mean;
            pmv[t] = mean;
            prv[t] = rsqrtf(var + 1e-5f);
        }
        __syncthreads();
        #pragma unroll
        for (int mi = 0; mi < 4; mi++) {
            #pragma unroll
            for (int hh = 0; hh < 2; hh++) {
                int lrow = wm*64 + mi*16 + g + hh*8;
                size_t m = (size_t)(m0 + lrow);
                float mean = pmv[lrow], r = prv[lrow];
                #pragma unroll
                for (int ni = 0; ni < 8; ni++) {
                    int col = wn*64 + ni*8 + 2*tig;
                    float2 o;
                    o.x = (c_[mi][ni][hh*2+0] - mean) * r * gm[ni][0] + bt[ni][0];
                    o.y = (c_[mi][ni][hh*2+1] - mean) * r * gm[ni][1] + bt[ni][1];
                    *(float2*)(C + m*128 + col) = o;
                    *(__half2*)(C16 + m*128 + col) = __floats2half2_rn(o.x, o.y);
                }
            }
        }
    } else {
        #pragma unroll
        for (int mi = 0; mi < 4; mi++) {
            #pragma unroll
            for (int hh = 0; hh < 2; hh++) {
                size_t m = (size_t)(m0 + wm*64 + mi*16 + g + hh*8);
                #pragma unroll
                for (int ni = 0; ni < 8; ni++) {
                    int col = n0 + wn*64 + ni*8 + 2*tig;
                    float v0 = c_[mi][ni][hh*2+0];
                    float v1 = c_[mi][ni][hh*2+1];
                    if (EPI == 1) {
                        v0 = fmaxf(v0 + bias[col],   0.f);
                        v1 = fmaxf(v1 + bias[col+1], 0.f);
                        *(__half2*)(C16 + m * Ndim + col) = __floats2half2_rn(v0, v1);
                    } else {
                        float2 o; o.x = v0; o.y = v1;
                        *(float2*)(C + m * Ndim + col) = o;
                    }
                }
            }
        }
    }
}

struct Ptr8 { const uint32_t* w[4]; float* c[4]; };

__global__ void __launch_bounds__(128, 2) sgemm4_kernel(const __half* A16, Ptr8 p)
{
    mma_core<0>(A16, p.w[blockIdx.z], p.c[blockIdx.z], nullptr, nullptr, nullptr, nullptr,
                128, 128, blockIdx.y * 128, 0);
}
__global__ void __launch_bounds__(128, 2) sgemm_bias_relu_kernel(const __half* A16, const uint32_t* W16,
                                                                 __half* C16, const float* bias,
                                                                 int Ndim, int Kdim)
{
    mma_core<1>(A16, W16, nullptr, C16, bias, nullptr, nullptr, Ndim, Kdim,
                blockIdx.y * 128, blockIdx.x * 128);
}
__global__ void __launch_bounds__(128, 2) sgemm_ln_kernel(const __half* A16, const uint32_t* W16,
                                                          float* TOK, __half* TOK16, const float* bias,
                                                          const float* gamma, const float* beta,
                                                          int Kdim)
{
    mma_core<2>(A16, W16, TOK, TOK16, bias, gamma, beta, 128, Kdim, blockIdx.y * 128, 0);
}

// ---------------- attention scores: s[b,h,l,i,j] = Q_l @ K_l^T / sqrt(DH) ----------------
__global__ void __launch_bounds__(256) scores_kernel()
{
    int lin = blockIdx.x;          // (b,h,l)
    int l = lin & 63, h = (lin >> 6) & 3, b = lin >> 8;
    __shared__ float Qs[32][68];   // [d][i]
    __shared__ float Ks[32][68];   // [d][j]
    for (int e = threadIdx.x; e < 2048; e += 256) {
        int i = e >> 5, d = e & 31;
        Qs[d][i] = g_q[((size_t)((b*64+i)*64 + l))*128 + h*32 + d];
        Ks[d][i] = g_k[((size_t)((b*64+l)*64 + i))*128 + h*32 + d];
    }
    __syncthreads();
    int ti = threadIdx.x >> 4, tj = threadIdx.x & 15;
    int i0 = ti*4, j0 = tj*4;
    float acc[4][4];
    #pragma unroll
    for (int a = 0; a < 4; a++)
        #pragma unroll
        for (int c = 0; c < 4; c++) acc[a][c] = 0.f;
    #pragma unroll
    for (int d = 0; d < 32; d++) {
        float4 ra = *(const float4*)&Qs[d][i0];
        float4 rb = *(const float4*)&Ks[d][j0];
        float A[4] = {ra.x, ra.y, ra.z, ra.w};
        float Bv[4] = {rb.x, rb.y, rb.z, rb.w};
        #pragma unroll
        for (int ii = 0; ii < 4; ii++)
            #pragma unroll
            for (int jj = 0; jj < 4; jj++)
                acc[ii][jj] += A[ii] * Bv[jj];
    }
    const float isc = 0.17677669529663687f;   // 1/sqrt(32)
    float* sp = g_s + ((size_t)((b*4+h)*64 + l)) * 4096;
    #pragma unroll
    for (int ii = 0; ii < 4; ii++) {
        float4 v = make_float4(acc[ii][0]*isc, acc[ii][1]*isc, acc[ii][2]*isc, acc[ii][3]*isc);
        *(float4*)(sp + (i0+ii)*64 + j0) = v;
    }
}

// ---------------- combine + fused softmax over l (Round-9 best variant; fp16 output) ----------------
#define CMB_SMEM ((16384 + 8192 + 256) * 4)
__global__ void __launch_bounds__(512, 2) combine_kernel()
{
    extern __shared__ float smc[];
    float* a4   = smc;            // [l*256 + j*4 + ii]  raw s -> exp(s - max)
    float* v1s  = smc + 16384;    // [ii*2048 + l*32 + d]
    float* invs = smc + 24576;    // [j*4 + ii] = 1/sum

    int lin = blockIdx.x;        // (b,h,i4)
    int i4 = lin & 15, h = (lin >> 4) & 3, b = lin >> 6;
    int t = threadIdx.x;
    int j = t >> 3, dg = t & 7;  // dg 0..7, 4 d's each

    const float* abase = g_s + ((size_t)(b*4+h))*262144;
    for (int e = t; e < 16384; e += 512) {
        int ii = e >> 12, l = (e >> 6) & 63, jj = e & 63;
        a4[l*256 + jj*4 + ii] = abase[(size_t)l*4096 + (i4*4+ii)*64 + jj];
    }
    for (int e = t; e < 8192; e += 512) {
        int ii = e >> 11, l = (e >> 5) & 63, d = e & 31;
        v1s[ii*2048 + l*32 + d] = g_v1[((size_t)((b*64+i4*4+ii)*64 + l))*128 + h*32 + d];
    }
    __syncthreads();   // a4/v1s visible

    {
        int col = t >> 1, half = t & 1;     // col 0..255 -> (j = col>>2, ii = col&3)
        float* sp = a4 + col + half*32*256;
        float mx = -1e30f;
        #pragma unroll 4
        for (int l = 0; l < 32; l++) mx = fmaxf(mx, sp[l*256]);
        mx = fmaxf(mx, __shfl_xor_sync(0xffffffffu, mx, 1));
        float sum = 0.f;
        #pragma unroll 4
        for (int l = 0; l < 32; l++) { float e = __expf(sp[l*256] - mx); sp[l*256] = e; sum += e; }
        sum += __shfl_xor_sync(0xffffffffu, sum, 1);
        if (half == 0) invs[col] = 1.f / sum;
    }
    __syncthreads();

    float acc[4][4];
    #pragma unroll
    for (int ii = 0; ii < 4; ii++)
        #pragma unroll
        for (int k = 0; k < 4; k++) acc[ii][k] = 0.f;

    const float* v2p = g_v2 + ((size_t)(b*64)*64 + j)*128 + h*32 + dg*4;
    const size_t v2step = (size_t)64*128;

    float4 nv0 = *(const float4*)(v2p);              // prefetch l=0
    float4 nv1 = *(const float4*)(v2p + v2step);     // prefetch l=1
    #pragma unroll 2
    for (int l = 0; l < 64; l += 2) {
        float4 va = nv0, vb = nv1;
        if (l + 2 < 64) nv0 = *(const float4*)(v2p + (size_t)(l+2)*v2step);
        if (l + 3 < 64) nv1 = *(const float4*)(v2p + (size_t)(l+3)*v2step);
        {
            float4 av4 = *(const float4*)&a4[l*256 + j*4];
            float aa[4] = {av4.x, av4.y, av4.z, av4.w};
            #pragma unroll
            for (int ii = 0; ii < 4; ii++) {
                const float4 v1v = *(const float4*)&v1s[ii*2048 + l*32 + dg*4];
                acc[ii][0] += aa[ii] * v1v.x * va.x;
                acc[ii][1] += aa[ii] * v1v.y * va.y;
                acc[ii][2] += aa[ii] * v1v.z * va.z;
                acc[ii][3] += aa[ii] * v1v.w * va.w;
            }
        }
        {
            float4 av4 = *(const float4*)&a4[(l+1)*256 + j*4];
            float aa[4] = {av4.x, av4.y, av4.z, av4.w};
            #pragma unroll
            for (int ii = 0; ii < 4; ii++) {
                const float4 v1v = *(const float4*)&v1s[ii*2048 + (l+1)*32 + dg*4];
                acc[ii][0] += aa[ii] * v1v.x * vb.x;
                acc[ii][1] += aa[ii] * v1v.y * vb.y;
                acc[ii][2] += aa[ii] * v1v.z * vb.z;
                acc[ii][3] += aa[ii] * v1v.w * vb.w;
            }
        }
    }

    float4 iv = *(const float4*)&invs[j*4];
    float inv4[4] = {iv.x, iv.y, iv.z, iv.w};

    #pragma unroll
    for (int ii = 0; ii < 4; ii++) {
        int i = i4*4 + ii;
        __half* op = g_o16 + ((size_t)((b*64+i)*64 + j))*128 + h*32 + dg*4;
        *(__half2*)(op)     = __floats2half2_rn(acc[ii][0]*inv4[ii], acc[ii][1]*inv4[ii]);
        *(__half2*)(op + 2) = __floats2half2_rn(acc[ii][2]*inv4[ii], acc[ii][3]*inv4[ii]);
    }
}

// ---------------- final head: out[b,n] = tok[b,n,n,:] @ Wout + bout ----------------
__global__ void out_kernel(const float* __restrict__ Wout, const float* __restrict__ bout,
                           float* __restrict__ out)
{
    int bn = blockIdx.x, d = threadIdx.x;
    int b = bn >> 6, n = bn & 63;
    float v = g_tok[((size_t)((b*64+n)*64 + n))*128 + d] * Wout[d];
    #pragma unroll
    for (int o = 16; o; o >>= 1) v += __shfl_xor_sync(0xffffffffu, v, o);
    __shared__ float ws[4];
    if ((d & 31) == 0) ws[d >> 5] = v;
    __syncthreads();
    if (d == 0) out[bn] = ws[0] + ws[1] + ws[2] + ws[3] + bout[0];
}

// ---------------- host orchestration ----------------
extern "C" void kernel_launch(void* const* d_in, const int* in_sizes, int n_in,
                              void* d_out, int out_size)
{
    const float* x    = (const float*)d_in[0];
    const float* ea   = (const float*)d_in[1];
    const int*   mask = (const int*)d_in[2];
    const float* nW   = (const float*)d_in[3];
    const float* nb   = (const float*)d_in[4];
    const float* eW   = (const float*)d_in[5];
    const float* eb   = (const float*)d_in[6];
    const float* noe  = (const float*)d_in[7];
    const float* Wq   = (const float*)d_in[8];
    const float* Wk   = (const float*)d_in[9];
    const float* Wv1  = (const float*)d_in[10];
    const float* Wv2  = (const float*)d_in[11];
    const float* Wo   = (const float*)d_in[12];
    const float* bo   = (const float*)d_in[13];
    const float* ln1g = (const float*)d_in[14];
    const float* ln1b = (const float*)d_in[15];
    const float* W1   = (const float*)d_in[16];
    const float* b1   = (const float*)d_in[17];
    const float* W2   = (const float*)d_in[18];
    const float* b2   = (const float*)d_in[19];
    const float* ln2g = (const float*)d_in[20];
    const float* ln2b = (const float*)d_in[21];
    const float* Wout = (const float*)d_in[22];
    const float* bout = (const float*)d_in[23];
    float* out = (float*)d_out;

    float *tok, *q, *k, *v1, *v2;
    __half *tok16, *o16, *hid16, *w16h;
    cudaGetSymbolAddress((void**)&tok,   g_tok);
    cudaGetSymbolAddress((void**)&tok16, g_tok16);
    cudaGetSymbolAddress((void**)&q,   g_q);
    cudaGetSymbolAddress((void**)&k,   g_k);
    cudaGetSymbolAddress((void**)&v1,  g_v1);
    cudaGetSymbolAddress((void**)&v2,  g_v2);
    cudaGetSymbolAddress((void**)&o16, g_o16);
    cudaGetSymbolAddress((void**)&hid16, g_hid16);
    cudaGetSymbolAddress((void**)&w16h, g_w16);
    const uint32_t* w16 = (const uint32_t*)w16h;   // u32 view of packed fp16

    cudaFuncSetAttribute(combine_kernel, cudaFuncAttributeMaxDynamicSharedMemorySize, CMB_SMEM);
    cudaFuncSetAttribute(sgemm4_kernel, cudaFuncAttributeMaxDynamicSharedMemorySize, GEMM_SMEM);
    cudaFuncSetAttribute(sgemm_bias_relu_kernel, cudaFuncAttributeMaxDynamicSharedMemorySize, GEMM_SMEM);
    cudaFuncSetAttribute(sgemm_ln_kernel, cudaFuncAttributeMaxDynamicSharedMemorySize, GEMM_SMEM);

    wconv_kernel<<<2496, 256>>>(Wq, Wk, Wv1, Wv2, Wo, W1, W2);
    embed_kernel<<<Mm, 128>>>(x, ea, mask, nW, nb, eW, eb, noe);

    // u32 offsets into g_w16 (half offsets / 2)
    const int OQ = 0, OK = 49152/2, OV1 = 98304/2, OV2 = 147456/2, OO = 196608/2;
    const int O1 = 245760/2, O2 = 442368/2;
    const int LW = 16384/2, LF = 65536/2;   // per-layer strides (u32)

    for (int l = 0; l < Llay; l++) {
        Ptr8 p;
        p.w[0] = w16 + OQ  + l*LW;
        p.w[1] = w16 + OK  + l*LW;
        p.w[2] = w16 + OV1 + l*LW;
        p.w[3] = w16 + OV2 + l*LW;
        p.c[0] = q; p.c[1] = k; p.c[2] = v1; p.c[3] = v2;
        sgemm4_kernel<<<dim3(1, Mm/128, 4), 128, GEMM_SMEM>>>(tok16, p);

        scores_kernel <<<Bb*Hh*Nn, 256>>>();
        combine_kernel<<<Bb*Hh*(Nn/4), 512, CMB_SMEM>>>();

        // tok = LN(tok + o@Wo + bo)   (fused epilogue; writes tok fp32 + tok16)
        sgemm_ln_kernel<<<dim3(1, Mm/128), 128, GEMM_SMEM>>>(o16, w16 + OO + l*LW, tok, tok16,
                                                  bo + l*128, ln1g + l*128, ln1b + l*128, 128);

        // ff
        sgemm_bias_relu_kernel<<<dim3(FFf/128, Mm/128), 128, GEMM_SMEM>>>(tok16, w16 + O1 + l*LF,
                                                               hid16, b1 + l*512, 512, 128);
        // tok = LN(tok + hid@W2 + b2) (fused epilogue)
        sgemm_ln_kernel<<<dim3(1, Mm/128), 128, GEMM_SMEM>>>(hid16, w16 + O2 + l*LF, tok, tok16,
                                                  b2 + l*128, ln2g + l*128, ln2b + l*128, 512);
    }

    out_kernel<<<Bb*Nn, 128>>>(Wout, bout, out);
}

// round 16
// speedup vs baseline: 1.2522x; 1.0784x over previous
#include <cuda_runtime.h>
#include <cuda_fp16.h>
#include <math.h>
#include <stdint.h>

// Problem constants
#define Bb   8
#define Nn   64
#define Dd   128
#define Hh   4
#define DHh  32
#define Llay 3
#define FFf  512
#define Mm   (Bb*Nn*Nn)   // 32768 tokens

// ---------------- scratch (device globals; no runtime allocation) ----------------
__device__ float  g_tok [Mm*Dd];           // fp32 tok (residual/LN/out)
__device__ __half g_tok16[Mm*Dd];          // fp16 shadow (GEMM A input)
__device__ __half g_q16[Mm*Dd];            // fp16 q (scores consumes)
__device__ __half g_k16[Mm*Dd];            // fp16 k (scores consumes)
__device__ float  g_v1 [Mm*Dd];
__device__ float  g_v2 [Mm*Dd];
__device__ float  g_s  [Bb*Hh*Nn*Nn*Nn];   // [b,h,l,i,j]
__device__ __half g_o16 [Mm*Dd];           // combine output (only GEMM consumes)
__device__ __half g_hid16[Mm*FFf];         // FF hidden (only GEMM consumes)
// packed fp16 weights: [k/2][n][2] per (weight, layer)
__device__ __half g_w16[638976];

// ---------------- helpers ----------------
__device__ __forceinline__ void mma16(float* c, const uint32_t* a, uint32_t b0, uint32_t b1) {
    asm volatile("mma.sync.aligned.m16n8k16.row.col.f32.f16.f16.f32 "
                 "{%0,%1,%2,%3}, {%4,%5,%6,%7}, {%8,%9}, {%0,%1,%2,%3};"
                 : "+f"(c[0]), "+f"(c[1]), "+f"(c[2]), "+f"(c[3])
                 : "r"(a[0]), "r"(a[1]), "r"(a[2]), "r"(a[3]), "r"(b0), "r"(b1));
}
__device__ __forceinline__ void cp16(void* dst_smem, const void* src) {
    uint32_t d = (uint32_t)__cvta_generic_to_shared(dst_smem);
    asm volatile("cp.async.cg.shared.global [%0], [%1], 16;" :: "r"(d), "l"(src) : "memory");
}
__device__ __forceinline__ void cp_commit() {
    asm volatile("cp.async.commit_group;" ::: "memory");
}
template<int N>
__device__ __forceinline__ void cp_wait() {
    asm volatile("cp.async.wait_group %0;" :: "n"(N) : "memory");
}

// ---------------- weight conversion: fp32 -> packed fp16 [k/2][n][2] ----------------
__global__ void wconv_kernel(const float* __restrict__ Wq, const float* __restrict__ Wk,
                             const float* __restrict__ Wv1, const float* __restrict__ Wv2,
                             const float* __restrict__ Wo, const float* __restrict__ W1,
                             const float* __restrict__ W2)
{
    int e = blockIdx.x*256 + threadIdx.x;
    if (e >= 638976) return;
    const float* src; int dst;
    if (e < 245760) {
        int seg = e / 49152, r = e % 49152;
        const float* tab[5] = {Wq, Wk, Wv1, Wv2, Wo};
        src = tab[seg] + r;
        int l = r >> 14, rr = r & 16383, k = rr >> 7, n = rr & 127;
        dst = seg*49152 + l*16384 + (k>>1)*256 + n*2 + (k&1);
    } else if (e < 442368) {
        int r = e - 245760;
        src = W1 + r;
        int l = r >> 16, rr = r & 65535, k = rr >> 9, n = rr & 511;
        dst = 245760 + l*65536 + (k>>1)*1024 + n*2 + (k&1);
    } else {
        int r = e - 442368;
        src = W2 + r;
        int l = r >> 16, rr = r & 65535, k = rr >> 7, n = rr & 127;
        dst = 442368 + l*65536 + (k>>1)*256 + n*2 + (k&1);
    }
    g_w16[dst] = __float2half(*src);
}

// ---------------- embedding ----------------
__global__ void embed_kernel(const float* __restrict__ x, const float* __restrict__ ea,
                             const int* __restrict__ mask,
                             const float* __restrict__ nW, const float* __restrict__ nb,
                             const float* __restrict__ eW, const float* __restrict__ eb,
                             const float* __restrict__ noe)
{
    int m = blockIdx.x;           // token index (b,i,j)
    int d = threadIdx.x;          // 0..127
    int b = m >> 12;
    int i = (m >> 6) & 63;
    int j = m & 63;
    __shared__ float in_s[16];
    float acc;
    if (i == j) {
        if (d < 16) in_s[d] = x[(b*64+i)*16 + d];
        __syncthreads();
        acc = nb[d];
        #pragma unroll
        for (int k = 0; k < 16; k++) acc += in_s[k] * nW[k*128 + d];
    } else if (mask[m] != 0) {
        if (d < 8) in_s[d] = ea[(size_t)m*8 + d];
        __syncthreads();
        acc = eb[d];
        #pragma unroll
        for (int k = 0; k < 8; k++) acc += in_s[k] * eW[k*128 + d];
    } else {
        acc = noe[d];
    }
    g_tok  [(size_t)m*128 + d] = acc;
    g_tok16[(size_t)m*128 + d] = __float2half(acc);
}

// ---------------- FP16 tensor-core GEMM: 128x128 CTA tile, BK=32, cp.async double-buffer ----------------
// 128 threads = 4 warps in 2(m) x 2(n); warp tile 64x64 via 4x8 m16n8k16 fragments.
// EPI: 0 = plain store (fp32 to C, or fp16 to C16 if C16 != null), 1 = bias+relu fp16 to C16,
//      2 = residual+bias+LN -> C fp32 + C16 fp16
#define AS_B   0
#define BS_B   20480
#define PS_B   37888
#define PS2_B  (PS_B + 1024)
#define PMV_B  (PS2_B + 1024)
#define PRV_B  (PMV_B + 512)
#define GEMM_SMEM (PRV_B + 512)     // 40448 bytes

template<int EPI>
__device__ __forceinline__ void mma_core(const __half* __restrict__ A16,
                                         const uint32_t* __restrict__ W16,
                                         float* __restrict__ C,
                                         __half* __restrict__ C16,
                                         const float* __restrict__ bias,
                                         const float* __restrict__ gamma,
                                         const float* __restrict__ beta,
                                         int Ndim, int Kdim, int m0, int n0)
{
    extern __shared__ char smraw[];
    __half*   As  = (__half*)(smraw + AS_B);    // [buf][m][40]
    uint32_t* Bs  = (uint32_t*)(smraw + BS_B);  // [buf][k2][136]
    float* ps  = (float*)(smraw + PS_B);
    float* ps2 = (float*)(smraw + PS2_B);
    float* pmv = (float*)(smraw + PMV_B);
    float* prv = (float*)(smraw + PRV_B);

    const int t    = threadIdx.x;
    const int lane = t & 31;
    const int w    = t >> 5;
    const int wm   = w >> 1;            // 0..1
    const int wn   = w & 1;             // 0..1
    const int g    = lane >> 2;         // 0..7
    const int tig  = lane & 3;          // 0..3

    float c_[4][8][4];
    #pragma unroll
    for (int mi = 0; mi < 4; mi++)
        #pragma unroll
        for (int ni = 0; ni < 8; ni++)
            #pragma unroll
            for (int r = 0; r < 4; r++) c_[mi][ni][r] = 0.f;

    auto issue = [&](int kb, int buf) {
        __half* Ab = As + buf*128*40;
        uint32_t* Bb_ = Bs + buf*16*136;
        #pragma unroll
        for (int q = 0; q < 4; q++) {          // A: 128 rows x 32 halfs = 512 chunks of 16B
            int idx = q*128 + t;
            int m = idx >> 2, c = idx & 3;
            cp16(Ab + m*40 + c*8, A16 + (size_t)(m0+m)*Kdim + kb*32 + c*8);
        }
        #pragma unroll
        for (int q = 0; q < 4; q++) {          // B: 16 k2-rows x 128 u32 = 512 chunks
            int idx = q*128 + t;
            int k2 = idx >> 5, c = idx & 31;
            cp16(Bb_ + k2*136 + c*4, W16 + (size_t)(kb*16+k2)*Ndim + n0 + c*4);
        }
        cp_commit();
    };

    issue(0, 0);
    const int nk = Kdim >> 5;
    for (int kb = 0; kb < nk; kb++) {
        const int cur = kb & 1;
        cp_wait<0>();
        __syncthreads();
        if (kb + 1 < nk) issue(kb+1, cur ^ 1);
        __half* Ab = As + cur*128*40;
        uint32_t* Bb_ = Bs + cur*16*136;

        #pragma unroll
        for (int s = 0; s < 2; s++) {          // two m16n8k16 steps per BK=32
            uint32_t af[4][4];
            #pragma unroll
            for (int mi = 0; mi < 4; mi++) {
                int mm = wm*64 + mi*16 + g;
                af[mi][0] = *(const uint32_t*)&Ab[(mm  )*40 + s*16 + 2*tig];
                af[mi][1] = *(const uint32_t*)&Ab[(mm+8)*40 + s*16 + 2*tig];
                af[mi][2] = *(const uint32_t*)&Ab[(mm  )*40 + s*16 + 2*tig + 8];
                af[mi][3] = *(const uint32_t*)&Ab[(mm+8)*40 + s*16 + 2*tig + 8];
            }
            uint32_t bf[8][2];
            #pragma unroll
            for (int ni = 0; ni < 8; ni++) {
                int nn = wn*64 + ni*8 + g;
                bf[ni][0] = Bb_[(s*8 + tig    )*136 + nn];
                bf[ni][1] = Bb_[(s*8 + tig + 4)*136 + nn];
            }
            #pragma unroll
            for (int mi = 0; mi < 4; mi++)
                #pragma unroll
                for (int ni = 0; ni < 8; ni++)
                    mma16(c_[mi][ni], af[mi], bf[ni][0], bf[ni][1]);
        }
    }

    if (EPI == 2) {
        float bi[8][2], gm[8][2], bt[8][2];
        #pragma unroll
        for (int ni = 0; ni < 8; ni++) {
            int col = wn*64 + ni*8 + 2*tig;
            float2 v;
            v = *(const float2*)(bias  + col); bi[ni][0] = v.x; bi[ni][1] = v.y;
            v = *(const float2*)(gamma + col); gm[ni][0] = v.x; gm[ni][1] = v.y;
            v = *(const float2*)(beta  + col); bt[ni][0] = v.x; bt[ni][1] = v.y;
        }
        #pragma unroll
        for (int mi = 0; mi < 4; mi++) {
            #pragma unroll
            for (int hh = 0; hh < 2; hh++) {
                int lrow = wm*64 + mi*16 + g + hh*8;
                size_t m = (size_t)(m0 + lrow);
                float s = 0.f, s2 = 0.f;
                #pragma unroll
                for (int ni = 0; ni < 8; ni++) {
                    int col = wn*64 + ni*8 + 2*tig;
                    float2 res = *(const float2*)(C + m*128 + col);
                    float v0 = c_[mi][ni][hh*2+0] + res.x + bi[ni][0];
                    float v1 = c_[mi][ni][hh*2+1] + res.y + bi[ni][1];
                    c_[mi][ni][hh*2+0] = v0;
                    c_[mi][ni][hh*2+1] = v1;
                    s += v0 + v1; s2 += v0*v0 + v1*v1;
                }
                s  += __shfl_xor_sync(0xffffffffu, s,  1);
                s  += __shfl_xor_sync(0xffffffffu, s,  2);
                s2 += __shfl_xor_sync(0xffffffffu, s2, 1);
                s2 += __shfl_xor_sync(0xffffffffu, s2, 2);
                if (tig == 0) { ps[lrow*2 + wn] = s; ps2[lrow*2 + wn] = s2; }
            }
        }
        __syncthreads();
        if (t < 128) {
            float s = ps[t*2+0] + ps[t*2+1];
            float s2 = ps2[t*2+0] + ps2[t*2+1];
            float mean = s * (1.f/128.f);
            float var  = s2 * (1.f/128.f) - mean*mean;
            pmv[t] = mean;
            prv[t] = rsqrtf(var + 1e-5f);
        }
        __syncthreads();
        #pragma unroll
        for (int mi = 0; mi < 4; mi++) {
            #pragma unroll
            for (int hh = 0; hh < 2; hh++) {
                int lrow = wm*64 + mi*16 + g + hh*8;
                size_t m = (size_t)(m0 + lrow);
                float mean = pmv[lrow], r = prv[lrow];
                #pragma unroll
                for (int ni = 0; ni < 8; ni++) {
                    int col = wn*64 + ni*8 + 2*tig;
                    float2 o;
                    o.x = (c_[mi][ni][hh*2+0] - mean) * r * gm[ni][0] + bt[ni][0];
                    o.y = (c_[mi][ni][hh*2+1] - mean) * r * gm[ni][1] + bt[ni][1];
                    *(float2*)(C + m*128 + col) = o;
                    *(__half2*)(C16 + m*128 + col) = __floats2half2_rn(o.x, o.y);
                }
            }
        }
    } else {
        #pragma unroll
        for (int mi = 0; mi < 4; mi++) {
            #pragma unroll
            for (int hh = 0; hh < 2; hh++) {
                size_t m = (size_t)(m0 + wm*64 + mi*16 + g + hh*8);
                #pragma unroll
                for (int ni = 0; ni < 8; ni++) {
                    int col = n0 + wn*64 + ni*8 + 2*tig;
                    float v0 = c_[mi][ni][hh*2+0];
                    float v1 = c_[mi][ni][hh*2+1];
                    if (EPI == 1) {
                        v0 = fmaxf(v0 + bias[col],   0.f);
                        v1 = fmaxf(v1 + bias[col+1], 0.f);
                        *(__half2*)(C16 + m * Ndim + col) = __floats2half2_rn(v0, v1);
                    } else {
                        if (C16) {
                            *(__half2*)(C16 + m * Ndim + col) = __floats2half2_rn(v0, v1);
                        } else {
                            float2 o; o.x = v0; o.y = v1;
                            *(float2*)(C + m * Ndim + col) = o;
                        }
                    }
                }
            }
        }
    }
}

struct Ptr8 { const uint32_t* w[4]; float* c[4]; __half* c16[4]; };

__global__ void __launch_bounds__(128, 2) sgemm4_kernel(const __half* A16, Ptr8 p)
{
    mma_core<0>(A16, p.w[blockIdx.z], p.c[blockIdx.z], p.c16[blockIdx.z],
                nullptr, nullptr, nullptr, 128, 128, blockIdx.y * 128, 0);
}
__global__ void __launch_bounds__(128, 2) sgemm_bias_relu_kernel(const __half* A16, const uint32_t* W16,
                                                                 __half* C16, const float* bias,
                                                                 int Ndim, int Kdim)
{
    mma_core<1>(A16, W16, nullptr, C16, bias, nullptr, nullptr, Ndim, Kdim,
                blockIdx.y * 128, blockIdx.x * 128);
}
__global__ void __launch_bounds__(128, 2) sgemm_ln_kernel(const __half* A16, const uint32_t* W16,
                                                          float* TOK, __half* TOK16, const float* bias,
                                                          const float* gamma, const float* beta,
                                                          int Kdim)
{
    mma_core<2>(A16, W16, TOK, TOK16, bias, gamma, beta, 128, Kdim, blockIdx.y * 128, 0);
}

// ---------------- attention scores via fp16 MMA: s[b,h,l,i,j] = Q_l @ K_l^T / sqrt(DH) ----------------
// Per CTA: (b,h,l), 64x64x32 GEMM. 128 threads = 4 warps; warp w does rows w*16..w*16+15.
__global__ void __launch_bounds__(128) scores_kernel(const __half* __restrict__ q16,
                                                     const __half* __restrict__ k16)
{
    __shared__ __half   Qs[64*40];     // [i][40]
    __shared__ uint32_t Ks[16*72];     // [d2][72]
    int lin = blockIdx.x;          // (b,h,l)
    int l = lin & 63, h = (lin >> 6) & 3, b = lin >> 8;
    int t = threadIdx.x;

    // Q rows: token (b*64+i)*64 + l, 32 halfs at h*32; 4x16B chunks per row
    const __half* qbase = q16 + ((size_t)(b*64)*64 + l)*128 + h*32;
    #pragma unroll
    for (int q = 0; q < 2; q++) {
        int e = q*128 + t;
        int i = e >> 2, c = e & 3;
        *(uint4*)&Qs[i*40 + c*8] = *(const uint4*)(qbase + (size_t)i*64*128 + c*8);
    }
    // K transposed: token (b*64+l)*64 + j; u32 pair d2 -> Ks[d2][j]
    const uint32_t* kbase = (const uint32_t*)(k16 + ((size_t)(b*64+l)*64)*128 + h*32);
    #pragma unroll
    for (int q = 0; q < 8; q++) {
        int e = q*128 + t;
        int j = e >> 4, d2 = e & 15;
        Ks[d2*72 + j] = kbase[j*64 + d2];
    }
    __syncthreads();

    int lane = t & 31, w = t >> 5;
    int g = lane >> 2, tig = lane & 3;
    float c_[8][4];
    #pragma unroll
    for (int ni = 0; ni < 8; ni++)
        #pragma unroll
        for (int r = 0; r < 4; r++) c_[ni][r] = 0.f;

    #pragma unroll
    for (int s = 0; s < 2; s++) {
        uint32_t af[4];
        int mm = w*16 + g;
        af[0] = *(const uint32_t*)&Qs[(mm  )*40 + s*16 + 2*tig];
        af[1] = *(const uint32_t*)&Qs[(mm+8)*40 + s*16 + 2*tig];
        af[2] = *(const uint32_t*)&Qs[(mm  )*40 + s*16 + 2*tig + 8];
        af[3] = *(const uint32_t*)&Qs[(mm+8)*40 + s*16 + 2*tig + 8];
        #pragma unroll
        for (int ni = 0; ni < 8; ni++) {
            uint32_t b0 = Ks[(s*8 + tig    )*72 + ni*8 + g];
            uint32_t b1 = Ks[(s*8 + tig + 4)*72 + ni*8 + g];
            mma16(c_[ni], af, b0, b1);
        }
    }

    const float isc = 0.17677669529663687f;   // 1/sqrt(32)
    float* sp = g_s + ((size_t)((b*4+h)*64 + l)) * 4096;
    int row0 = w*16 + g;
    #pragma unroll
    for (int ni = 0; ni < 8; ni++) {
        int col = ni*8 + 2*tig;
        float2 o0; o0.x = c_[ni][0]*isc; o0.y = c_[ni][1]*isc;
        float2 o1; o1.x = c_[ni][2]*isc; o1.y = c_[ni][3]*isc;
        *(float2*)(sp + row0*64 + col)     = o0;
        *(float2*)(sp + (row0+8)*64 + col) = o1;
    }
}

// ---------------- combine + fused softmax over l (Round-9 best variant; fp16 output) ----------------
#define CMB_SMEM ((16384 + 8192 + 256) * 4)
__global__ void __launch_bounds__(512, 2) combine_kernel()
{
    extern __shared__ float smc[];
    float* a4   = smc;            // [l*256 + j*4 + ii]  raw s -> exp(s - max)
    float* v1s  = smc + 16384;    // [ii*2048 + l*32 + d]
    float* invs = smc + 24576;    // [j*4 + ii] = 1/sum

    int lin = blockIdx.x;        // (b,h,i4)
    int i4 = lin & 15, h = (lin >> 4) & 3, b = lin >> 6;
    int t = threadIdx.x;
    int j = t >> 3, dg = t & 7;  // dg 0..7, 4 d's each

    const float* abase = g_s + ((size_t)(b*4+h))*262144;
    for (int e = t; e < 16384; e += 512) {
        int ii = e >> 12, l = (e >> 6) & 63, jj = e & 63;
        a4[l*256 + jj*4 + ii] = abase[(size_t)l*4096 + (i4*4+ii)*64 + jj];
    }
    for (int e = t; e < 8192; e += 512) {
        int ii = e >> 11, l = (e >> 5) & 63, d = e & 31;
        v1s[ii*2048 + l*32 + d] = g_v1[((size_t)((b*64+i4*4+ii)*64 + l))*128 + h*32 + d];
    }
    __syncthreads();   // a4/v1s visible

    {
        int col = t >> 1, half = t & 1;     // col 0..255 -> (j = col>>2, ii = col&3)
        float* sp = a4 + col + half*32*256;
        float mx = -1e30f;
        #pragma unroll 4
        for (int l = 0; l < 32; l++) mx = fmaxf(mx, sp[l*256]);
        mx = fmaxf(mx, __shfl_xor_sync(0xffffffffu, mx, 1));
        float sum = 0.f;
        #pragma unroll 4
        for (int l = 0; l < 32; l++) { float e = __expf(sp[l*256] - mx); sp[l*256] = e; sum += e; }
        sum += __shfl_xor_sync(0xffffffffu, sum, 1);
        if (half == 0) invs[col] = 1.f / sum;
    }
    __syncthreads();

    float acc[4][4];
    #pragma unroll
    for (int ii = 0; ii < 4; ii++)
        #pragma unroll
        for (int k = 0; k < 4; k++) acc[ii][k] = 0.f;

    const float* v2p = g_v2 + ((size_t)(b*64)*64 + j)*128 + h*32 + dg*4;
    const size_t v2step = (size_t)64*128;

    float4 nv0 = *(const float4*)(v2p);              // prefetch l=0
    float4 nv1 = *(const float4*)(v2p + v2step);     // prefetch l=1
    #pragma unroll 2
    for (int l = 0; l < 64; l += 2) {
        float4 va = nv0, vb = nv1;
        if (l + 2 < 64) nv0 = *(const float4*)(v2p + (size_t)(l+2)*v2step);
        if (l + 3 < 64) nv1 = *(const float4*)(v2p + (size_t)(l+3)*v2step);
        {
            float4 av4 = *(const float4*)&a4[l*256 + j*4];
            float aa[4] = {av4.x, av4.y, av4.z, av4.w};
            #pragma unroll
            for (int ii = 0; ii < 4; ii++) {
                const float4 v1v = *(const float4*)&v1s[ii*2048 + l*32 + dg*4];
                acc[ii][0] += aa[ii] * v1v.x * va.x;
                acc[ii][1] += aa[ii] * v1v.y * va.y;
                acc[ii][2] += aa[ii] * v1v.z * va.z;
                acc[ii][3] += aa[ii] * v1v.w * va.w;
            }
        }
        {
            float4 av4 = *(const float4*)&a4[(l+1)*256 + j*4];
            float aa[4] = {av4.x, av4.y, av4.z, av4.w};
            #pragma unroll
            for (int ii = 0; ii < 4; ii++) {
                const float4 v1v = *(const float4*)&v1s[ii*2048 + (l+1)*32 + dg*4];
                acc[ii][0] += aa[ii] * v1v.x * vb.x;
                acc[ii][1] += aa[ii] * v1v.y * vb.y;
                acc[ii][2] += aa[ii] * v1v.z * vb.z;
                acc[ii][3] += aa[ii] * v1v.w * vb.w;
            }
        }
    }

    float4 iv = *(const float4*)&invs[j*4];
    float inv4[4] = {iv.x, iv.y, iv.z, iv.w};

    #pragma unroll
    for (int ii = 0; ii < 4; ii++) {
        int i = i4*4 + ii;
        __half* op = g_o16 + ((size_t)((b*64+i)*64 + j))*128 + h*32 + dg*4;
        *(__half2*)(op)     = __floats2half2_rn(acc[ii][0]*inv4[ii], acc[ii][1]*inv4[ii]);
        *(__half2*)(op + 2) = __floats2half2_rn(acc[ii][2]*inv4[ii], acc[ii][3]*inv4[ii]);
    }
}

// ---------------- final head: out[b,n] = tok[b,n,n,:] @ Wout + bout ----------------
__global__ void out_kernel(const float* __restrict__ Wout, const float* __restrict__ bout,
                           float* __restrict__ out)
{
    int bn = blockIdx.x, d = threadIdx.x;
    int b = bn >> 6, n = bn & 63;
    float v = g_tok[((size_t)((b*64+n)*64 + n))*128 + d] * Wout[d];
    #pragma unroll
    for (int o = 16; o; o >>= 1) v += __shfl_xor_sync(0xffffffffu, v, o);
    __shared__ float ws[4];
    if ((d & 31) == 0) ws[d >> 5] = v;
    __syncthreads();
    if (d == 0) out[bn] = ws[0] + ws[1] + ws[2] + ws[3] + bout[0];
}

// ---------------- host orchestration ----------------
extern "C" void kernel_launch(void* const* d_in, const int* in_sizes, int n_in,
                              void* d_out, int out_size)
{
    const float* x    = (const float*)d_in[0];
    const float* ea   = (const float*)d_in[1];
    const int*   mask = (const int*)d_in[2];
    const float* nW   = (const float*)d_in[3];
    const float* nb   = (const float*)d_in[4];
    const float* eW   = (const float*)d_in[5];
    const float* eb   = (const float*)d_in[6];
    const float* noe  = (const float*)d_in[7];
    const float* Wq   = (const float*)d_in[8];
    const float* Wk   = (const float*)d_in[9];
    const float* Wv1  = (const float*)d_in[10];
    const float* Wv2  = (const float*)d_in[11];
    const float* Wo   = (const float*)d_in[12];
    const float* bo   = (const float*)d_in[13];
    const float* ln1g = (const float*)d_in[14];
    const float* ln1b = (const float*)d_in[15];
    const float* W1   = (const float*)d_in[16];
    const float* b1   = (const float*)d_in[17];
    const float* W2   = (const float*)d_in[18];
    const float* b2   = (const float*)d_in[19];
    const float* ln2g = (const float*)d_in[20];
    const float* ln2b = (const float*)d_in[21];
    const float* Wout = (const float*)d_in[22];
    const float* bout = (const float*)d_in[23];
    float* out = (float*)d_out;

    float *tok, *v1, *v2;
    __half *tok16, *q16, *k16, *o16, *hid16, *w16h;
    cudaGetSymbolAddress((void**)&tok,   g_tok);
    cudaGetSymbolAddress((void**)&tok16, g_tok16);
    cudaGetSymbolAddress((void**)&q16, g_q16);
    cudaGetSymbolAddress((void**)&k16, g_k16);
    cudaGetSymbolAddress((void**)&v1,  g_v1);
    cudaGetSymbolAddress((void**)&v2,  g_v2);
    cudaGetSymbolAddress((void**)&o16, g_o16);
    cudaGetSymbolAddress((void**)&hid16, g_hid16);
    cudaGetSymbolAddress((void**)&w16h, g_w16);
    const uint32_t* w16 = (const uint32_t*)w16h;   // u32 view of packed fp16

    cudaFuncSetAttribute(combine_kernel, cudaFuncAttributeMaxDynamicSharedMemorySize, CMB_SMEM);
    cudaFuncSetAttribute(sgemm4_kernel, cudaFuncAttributeMaxDynamicSharedMemorySize, GEMM_SMEM);
    cudaFuncSetAttribute(sgemm_bias_relu_kernel, cudaFuncAttributeMaxDynamicSharedMemorySize, GEMM_SMEM);
    cudaFuncSetAttribute(sgemm_ln_kernel, cudaFuncAttributeMaxDynamicSharedMemorySize, GEMM_SMEM);

    wconv_kernel<<<2496, 256>>>(Wq, Wk, Wv1, Wv2, Wo, W1, W2);
    embed_kernel<<<Mm, 128>>>(x, ea, mask, nW, nb, eW, eb, noe);

    // u32 offsets into g_w16 (half offsets / 2)
    const int OQ = 0, OK = 49152/2, OV1 = 98304/2, OV2 = 147456/2, OO = 196608/2;
    const int O1 = 245760/2, O2 = 442368/2;
    const int LW = 16384/2, LF = 65536/2;   // per-layer strides (u32)

    for (int l = 0; l < Llay; l++) {
        Ptr8 p;
        p.w[0] = w16 + OQ  + l*LW;
        p.w[1] = w16 + OK  + l*LW;
        p.w[2] = w16 + OV1 + l*LW;
        p.w[3] = w16 + OV2 + l*LW;
        p.c[0] = nullptr; p.c[1] = nullptr; p.c[2] = v1; p.c[3] = v2;
        p.c16[0] = q16; p.c16[1] = k16; p.c16[2] = nullptr; p.c16[3] = nullptr;
        sgemm4_kernel<<<dim3(1, Mm/128, 4), 128, GEMM_SMEM>>>(tok16, p);

        scores_kernel <<<Bb*Hh*Nn, 128>>>(q16, k16);
        combine_kernel<<<Bb*Hh*(Nn/4), 512, CMB_SMEM>>>();

        // tok = LN(tok + o@Wo + bo)   (fused epilogue; writes tok fp32 + tok16)
        sgemm_ln_kernel<<<dim3(1, Mm/128), 128, GEMM_SMEM>>>(o16, w16 + OO + l*LW, tok, tok16,
                                                  bo + l*128, ln1g + l*128, ln1b + l*128, 128);

        // ff
        sgemm_bias_relu_kernel<<<dim3(FFf/128, Mm/128), 128, GEMM_SMEM>>>(tok16, w16 + O1 + l*LF,
                                                               hid16, b1 + l*512, 512, 128);
        // tok = LN(tok + hid@W2 + b2) (fused epilogue)
        sgemm_ln_kernel<<<dim3(1, Mm/128), 128, GEMM_SMEM>>>(hid16, w16 + O2 + l*LF, tok, tok16,
                                                  b2 + l*128, ln2g + l*128, ln2b + l*128, 512);
    }

    out_kernel<<<Bb*Nn, 128>>>(Wout, bout, out);
}